// round 9
// baseline (speedup 1.0000x reference)
#include <cuda_runtime.h>
#include <float.h>

// Problem constants (from reference)
#define B_      8
#define L_      2048
#define D_      256
#define T_      32
#define S_PARA  8
#define S_ADU   24
#define S_SHELL 24

#define D4      (D_ / 4)          // 64 float4 columns per row
#define ROWS_TOPIC  (B_)                  // 8
#define ROWS_PARA   (B_ * S_PARA)         // 64
#define ROWS_SHELL  (B_ * S_SHELL)        // 192
#define ROWS_ADU    (B_ * S_ADU)          // 192
#define ROWS_TOTAL  (ROWS_TOPIC + ROWS_PARA + ROWS_SHELL + ROWS_ADU)  // 456

// flat output offsets (float elements), reference return order:
// (topic_out, para_reps, span_reps<-shell, adu_reps<-x)
#define OFF_TOPIC 0
#define OFF_PARA  (B_ * D_)                              // 2048
#define OFF_SHELL (OFF_PARA + B_ * S_PARA * D_)          // 18432
#define OFF_ADU   (OFF_SHELL + B_ * S_SHELL * D_)        // 67584

__device__ __forceinline__ float4 f4max(float4 a, float4 b) {
    float4 r;
    r.x = fmaxf(a.x, b.x);
    r.y = fmaxf(a.y, b.y);
    r.z = fmaxf(a.z, b.z);
    r.w = fmaxf(a.w, b.w);
    return r;
}

__device__ __forceinline__ float4 shfl_xor_f4(float4 v, int m) {
    float4 r;
    r.x = __shfl_xor_sync(0xffffffffu, v.x, m);
    r.y = __shfl_xor_sync(0xffffffffu, v.y, m);
    r.z = __shfl_xor_sync(0xffffffffu, v.z, m);
    r.w = __shfl_xor_sync(0xffffffffu, v.w, m);
    return r;
}

// One block per output row. Thread t owns float4-column (t>>2) and
// span-slice ys = t&3. No smem, no barriers, no atomics, no scratch.
__global__ __launch_bounds__(256) void span_maxpool_shfl_kernel(
    const float* __restrict__ topic_reps,   // [B,T,D]
    const float* __restrict__ word_reps,    // [B,L,D]
    const int*   __restrict__ para_spans,   // [B,S_PARA,3]
    const int*   __restrict__ x_spans,      // [B,S_ADU,3]
    const int*   __restrict__ shell_spans,  // [B,S_SHELL,3]
    float*       __restrict__ out)
{
    const int row = blockIdx.x;             // 0..455 (one output row per block)
    const int t   = threadIdx.x;
    const int col = t >> 2;                 // float4 column 0..63
    const int ys  = t & 3;                  // span-dim slice 0..3

    const float4* src;      // first pooled row, at this column
    int cnt;                // rows to pool (>=1)
    int out_off;            // flat float offset of output row

    if (row < ROWS_TOPIC) {
        src = (const float4*)(topic_reps + (size_t)row * T_ * D_) + col;
        cnt = T_;
        out_off = OFF_TOPIC + row * D_;
    } else if (row < ROWS_TOPIC + ROWS_PARA) {
        const int i = row - ROWS_TOPIC;
        const int* sp = para_spans + i * 3;
        src = (const float4*)(word_reps + ((size_t)sp[0] * L_ + sp[1]) * D_) + col;
        cnt = sp[2] - sp[1] + 1;
        out_off = OFF_PARA + i * D_;
    } else if (row < ROWS_TOPIC + ROWS_PARA + ROWS_SHELL) {
        const int i = row - (ROWS_TOPIC + ROWS_PARA);
        const int* sp = shell_spans + i * 3;
        src = (const float4*)(word_reps + ((size_t)sp[0] * L_ + sp[1]) * D_) + col;
        cnt = sp[2] - sp[1] + 1;
        out_off = OFF_SHELL + i * D_;
    } else {
        const int i = row - (ROWS_TOPIC + ROWS_PARA + ROWS_SHELL);
        const int* sp = x_spans + i * 3;
        src = (const float4*)(word_reps + ((size_t)sp[0] * L_ + sp[1]) * D_) + col;
        cnt = sp[2] - sp[1] + 1;
        out_off = OFF_ADU + i * D_;
    }

    const float4 neg = make_float4(-FLT_MAX, -FLT_MAX, -FLT_MAX, -FLT_MAX);
    float4 acc = neg;

    // ys-slice pools rows ys, ys+4, ys+8, ... in groups of 8 predicated
    // independent loads (32 rows of the span per iteration).
    // shell/topic: 1 iteration; adu: <=2; para: <=8.
    for (int r0 = ys; r0 < cnt; r0 += 32) {
        float4 v[8];
        #pragma unroll
        for (int j = 0; j < 8; j++) {
            const int r = r0 + j * 4;
            v[j] = (r < cnt) ? __ldg(src + (size_t)r * D4) : neg;
        }
        float4 a01 = f4max(v[0], v[1]);
        float4 a23 = f4max(v[2], v[3]);
        float4 a45 = f4max(v[4], v[5]);
        float4 a67 = f4max(v[6], v[7]);
        acc = f4max(acc, f4max(f4max(a01, a23), f4max(a45, a67)));
    }

    // Reduce across the 4 ys-slices within each warp (lanes 4k..4k+3
    // share a column): butterfly over xor 1 and 2.
    acc = f4max(acc, shfl_xor_f4(acc, 1));
    acc = f4max(acc, shfl_xor_f4(acc, 2));

    if (ys == 0) {
        ((float4*)(out + out_off))[col] = acc;
    }
}

extern "C" void kernel_launch(void* const* d_in, const int* in_sizes, int n_in,
                              void* d_out, int out_size) {
    // metadata order: topic_reps, word_reps, topic_lens(int64, unused),
    //                 para_spans, x_spans, shell_spans
    const float* topic_reps  = (const float*)d_in[0];
    const float* word_reps   = (const float*)d_in[1];
    const int*   para_spans  = (const int*)d_in[3];
    const int*   x_spans     = (const int*)d_in[4];
    const int*   shell_spans = (const int*)d_in[5];
    float* out = (float*)d_out;

    span_maxpool_shfl_kernel<<<ROWS_TOTAL, 256>>>(
        topic_reps, word_reps, para_spans, x_spans, shell_spans, out);
}

// round 10
// speedup vs baseline: 1.4588x; 1.4588x over previous
#include <cuda_runtime.h>
#include <float.h>

// Problem constants (from reference)
#define B_      8
#define L_      2048
#define D_      256
#define T_      32
#define S_PARA  8
#define S_ADU   24
#define S_SHELL 24

#define D4      (D_ / 4)          // 64 float4 columns per row
#define ROWS_PARA   (B_ * S_PARA)         // 64
#define ROWS_SHELL  (B_ * S_SHELL)        // 192
#define ROWS_ADU    (B_ * S_ADU)          // 192

// flat output offsets (float elements), reference return order:
// (topic_out, para_reps, span_reps<-shell, adu_reps<-x)
#define OFF_TOPIC 0
#define OFF_PARA  (B_ * D_)                              // 2048
#define OFF_SHELL (OFF_PARA + B_ * S_PARA * D_)          // 18432
#define OFF_ADU   (OFF_SHELL + B_ * S_SHELL * D_)        // 67584

#define YS 8              // span-dimension slices per block (512 threads)
#define PCHUNK 128        // para rows per chunk -> 16 rows/thread = 2 groups
#define PARA_CHUNKS 2     // 256 / 128

// block/slot layout (single kernel, 520 blocks x 512 threads):
//   [0, 8)      topic rows (32 rows)        -> direct out
//   [8, 136)    para chunks (64 x 2)        -> scratch + last-block reduce
//   [136, 328)  shell spans (<=16 rows)     -> direct out
//   [328, 520)  adu spans (<=64 rows)       -> direct out
#define SLOT_TOPIC 0
#define SLOT_PARA  8
#define SLOT_SHELL (SLOT_PARA + ROWS_PARA * PARA_CHUNKS)     // 136
#define SLOT_ADU   (SLOT_SHELL + ROWS_SHELL)                 // 328
#define SLOTS_TOTAL (SLOT_ADU + ROWS_ADU)                    // 520

__device__ float g_partial[ROWS_PARA * PARA_CHUNKS * D_];    // 128 KB
__device__ int   g_count[ROWS_PARA];                         // zero-init

__device__ __forceinline__ float4 f4max(float4 a, float4 b) {
    float4 r;
    r.x = fmaxf(a.x, b.x);
    r.y = fmaxf(a.y, b.y);
    r.z = fmaxf(a.z, b.z);
    r.w = fmaxf(a.w, b.w);
    return r;
}

__device__ __forceinline__ float4 ldcg4(const float4* p) {
    float4 v;
    asm volatile("ld.global.cg.v4.f32 {%0,%1,%2,%3}, [%4];"
                 : "=f"(v.x), "=f"(v.y), "=f"(v.z), "=f"(v.w) : "l"(p));
    return v;
}

__global__ __launch_bounds__(64 * YS) void span_maxpool_big_kernel(
    const float* __restrict__ topic_reps,   // [B,T,D]
    const float* __restrict__ word_reps,    // [B,L,D]
    const int*   __restrict__ para_spans,   // [B,S_PARA,3]
    const int*   __restrict__ x_spans,      // [B,S_ADU,3]
    const int*   __restrict__ shell_spans,  // [B,S_SHELL,3]
    float*       __restrict__ out)
{
    __shared__ float4 red[YS][D4];          // 8 KB
    __shared__ int s_last;

    const int slot = blockIdx.x;            // 0..519
    const int lane = threadIdx.x;           // 0..63 (contiguous float4 cols)
    const int ys   = threadIdx.y;           // 0..7

    const float4* src;      // first row of this block's range, at this lane
    int cnt;                // rows in range (<=0 possible for empty para chunk)
    int out_off = -1;       // direct-out offset (single-chunk slots)
    int para_i = -1;        // para span index (multi-chunk)
    int chunk_k = 0;        // para chunk id within scratch

    if (slot < SLOT_PARA) {
        src = (const float4*)(topic_reps + (size_t)slot * T_ * D_) + lane;
        cnt = T_;                           // 32
        out_off = OFF_TOPIC + slot * D_;
    } else if (slot < SLOT_SHELL) {
        const int k = slot - SLOT_PARA;     // 0..127
        para_i = k >> 1;                    // span 0..63
        const int c = k & 1;                // chunk 0..1
        chunk_k = k;
        const int* sp = para_spans + para_i * 3;
        src = (const float4*)(word_reps
              + ((size_t)sp[0] * L_ + sp[1] + c * PCHUNK) * D_) + lane;
        cnt = (sp[2] - sp[1] + 1) - c * PCHUNK;
        if (cnt > PCHUNK) cnt = PCHUNK;
    } else if (slot < SLOT_ADU) {
        const int i = slot - SLOT_SHELL;
        const int* sp = shell_spans + i * 3;
        src = (const float4*)(word_reps + ((size_t)sp[0] * L_ + sp[1]) * D_) + lane;
        cnt = sp[2] - sp[1] + 1;            // <= 16
        out_off = OFF_SHELL + i * D_;
    } else {
        const int i = slot - SLOT_ADU;
        const int* sp = x_spans + i * 3;
        src = (const float4*)(word_reps + ((size_t)sp[0] * L_ + sp[1]) * D_) + lane;
        cnt = sp[2] - sp[1] + 1;            // <= 64
        out_off = OFF_ADU + i * D_;
    }

    const float4 neg = make_float4(-FLT_MAX, -FLT_MAX, -FLT_MAX, -FLT_MAX);
    float4 acc = neg;

    // slice ys pools rows ys, ys+8, ... ; groups of 8 predicated independent
    // loads cover 64 rows/iteration. adu/shell/topic: 1 group; para: <=2.
    #pragma unroll 2
    for (int r0 = ys; r0 < cnt; r0 += 8 * YS) {
        float4 v[8];
        #pragma unroll
        for (int j = 0; j < 8; j++) {
            const int r = r0 + j * YS;
            v[j] = (r < cnt) ? __ldg(src + (size_t)r * D4) : neg;
        }
        float4 a01 = f4max(v[0], v[1]);
        float4 a23 = f4max(v[2], v[3]);
        float4 a45 = f4max(v[4], v[5]);
        float4 a67 = f4max(v[6], v[7]);
        acc = f4max(acc, f4max(f4max(a01, a23), f4max(a45, a67)));
    }

    red[ys][lane] = acc;
    __syncthreads();

    if (out_off >= 0) {
        // single-chunk slot: ys==0 slice (2 warps) combines 8 slices + stores
        if (ys == 0) {
            float4 r = f4max(f4max(f4max(red[0][lane], red[1][lane]),
                                   f4max(red[2][lane], red[3][lane])),
                             f4max(f4max(red[4][lane], red[5][lane]),
                                   f4max(red[6][lane], red[7][lane])));
            ((float4*)(out + out_off))[lane] = r;
        }
        return;
    }

    // ── para chunk: publish partial, last arriving block reduces (R5 tail) ──
    if (ys == 0) {
        float4 r = f4max(f4max(f4max(red[0][lane], red[1][lane]),
                               f4max(red[2][lane], red[3][lane])),
                         f4max(f4max(red[4][lane], red[5][lane]),
                               f4max(red[6][lane], red[7][lane])));
        ((float4*)(g_partial + (size_t)chunk_k * D_))[lane] = r;
        __threadfence();                    // publish before arrival
    }
    __syncthreads();

    if (threadIdx.x == 0 && threadIdx.y == 0) {
        int old = atomicAdd(&g_count[para_i], 1);
        s_last = (old == PARA_CHUNKS - 1);
    }
    __syncthreads();

    if (s_last) {
        if (ys == 0) {
            const float4* base = (const float4*)(g_partial
                                 + (size_t)(para_i * PARA_CHUNKS) * D_) + lane;
            float4 r = f4max(ldcg4(base), ldcg4(base + D4));
            ((float4*)(out + OFF_PARA + para_i * D_))[lane] = r;
        }
        if (threadIdx.x == 0 && threadIdx.y == 0) {
            g_count[para_i] = 0;            // reset for next graph replay
        }
    }
}

extern "C" void kernel_launch(void* const* d_in, const int* in_sizes, int n_in,
                              void* d_out, int out_size) {
    // metadata order: topic_reps, word_reps, topic_lens(int64, unused),
    //                 para_spans, x_spans, shell_spans
    const float* topic_reps  = (const float*)d_in[0];
    const float* word_reps   = (const float*)d_in[1];
    const int*   para_spans  = (const int*)d_in[3];
    const int*   x_spans     = (const int*)d_in[4];
    const int*   shell_spans = (const int*)d_in[5];
    float* out = (float*)d_out;

    dim3 block(64, YS);                // 512 threads
    span_maxpool_big_kernel<<<SLOTS_TOTAL, block>>>(
        topic_reps, word_reps, para_spans, x_spans, shell_spans, out);
}

// round 11
// speedup vs baseline: 1.4640x; 1.0036x over previous
#include <cuda_runtime.h>
#include <float.h>

// Problem constants (from reference)
#define B_      8
#define L_      2048
#define D_      256
#define T_      32
#define S_PARA  8
#define S_ADU   24
#define S_SHELL 24

#define D4      (D_ / 4)          // 64 float4 columns per row
#define ROWS_TOPIC  (B_)                  // 8
#define ROWS_PARA   (B_ * S_PARA)         // 64
#define ROWS_SHELL  (B_ * S_SHELL)        // 192
#define ROWS_ADU    (B_ * S_ADU)          // 192
#define ROWS_TOTAL  (ROWS_TOPIC + ROWS_PARA + ROWS_SHELL + ROWS_ADU)  // 456

// flat output offsets (float elements), reference return order:
// (topic_out, para_reps, span_reps<-shell, adu_reps<-x)
#define OFF_TOPIC 0
#define OFF_PARA  (B_ * D_)                              // 2048
#define OFF_SHELL (OFF_PARA + B_ * S_PARA * D_)          // 18432
#define OFF_ADU   (OFF_SHELL + B_ * S_SHELL * D_)        // 67584

#define YS 8              // span-dimension slices per block (512 threads)

__device__ __forceinline__ float4 f4max(float4 a, float4 b) {
    float4 r;
    r.x = fmaxf(a.x, b.x);
    r.y = fmaxf(a.y, b.y);
    r.z = fmaxf(a.z, b.z);
    r.w = fmaxf(a.w, b.w);
    return r;
}

// One block (512 threads) per output row. lane = contiguous float4 column,
// ys = span-dim slice. Zero atomics, zero fences, zero scratch, one barrier.
// Worst serial chain: para (<=256 rows) = 4 predicated 8-load groups.
__global__ __launch_bounds__(64 * YS) void span_maxpool_row_kernel(
    const float* __restrict__ topic_reps,   // [B,T,D]
    const float* __restrict__ word_reps,    // [B,L,D]
    const int*   __restrict__ para_spans,   // [B,S_PARA,3]
    const int*   __restrict__ x_spans,      // [B,S_ADU,3]
    const int*   __restrict__ shell_spans,  // [B,S_SHELL,3]
    float*       __restrict__ out)
{
    __shared__ float4 red[YS][D4];          // 8 KB

    const int row  = blockIdx.x;            // 0..455
    const int lane = threadIdx.x;           // 0..63 (contiguous float4 cols)
    const int ys   = threadIdx.y;           // 0..7

    const float4* src;      // first pooled row, at this lane
    int cnt;                // rows to pool (>=1)
    int out_off;            // flat float offset of output row

    if (row < ROWS_TOPIC) {
        src = (const float4*)(topic_reps + (size_t)row * T_ * D_) + lane;
        cnt = T_;
        out_off = OFF_TOPIC + row * D_;
    } else if (row < ROWS_TOPIC + ROWS_PARA) {
        const int i = row - ROWS_TOPIC;
        const int* sp = para_spans + i * 3;
        src = (const float4*)(word_reps + ((size_t)sp[0] * L_ + sp[1]) * D_) + lane;
        cnt = sp[2] - sp[1] + 1;            // <= 256
        out_off = OFF_PARA + i * D_;
    } else if (row < ROWS_TOPIC + ROWS_PARA + ROWS_SHELL) {
        const int i = row - (ROWS_TOPIC + ROWS_PARA);
        const int* sp = shell_spans + i * 3;
        src = (const float4*)(word_reps + ((size_t)sp[0] * L_ + sp[1]) * D_) + lane;
        cnt = sp[2] - sp[1] + 1;            // <= 16
        out_off = OFF_SHELL + i * D_;
    } else {
        const int i = row - (ROWS_TOPIC + ROWS_PARA + ROWS_SHELL);
        const int* sp = x_spans + i * 3;
        src = (const float4*)(word_reps + ((size_t)sp[0] * L_ + sp[1]) * D_) + lane;
        cnt = sp[2] - sp[1] + 1;            // <= 64
        out_off = OFF_ADU + i * D_;
    }

    const float4 neg = make_float4(-FLT_MAX, -FLT_MAX, -FLT_MAX, -FLT_MAX);
    float4 acc = neg;

    // Slice ys pools rows ys, ys+8, ... in groups of 8 predicated independent
    // loads (64 rows per iteration). shell/topic/adu: 1 iter; para: <=4.
    #pragma unroll 1
    for (int r0 = ys; r0 < cnt; r0 += 8 * YS) {
        float4 v[8];
        #pragma unroll
        for (int j = 0; j < 8; j++) {
            const int r = r0 + j * YS;
            v[j] = (r < cnt) ? __ldg(src + (size_t)r * D4) : neg;
        }
        float4 a01 = f4max(v[0], v[1]);
        float4 a23 = f4max(v[2], v[3]);
        float4 a45 = f4max(v[4], v[5]);
        float4 a67 = f4max(v[6], v[7]);
        acc = f4max(acc, f4max(f4max(a01, a23), f4max(a45, a67)));
    }

    red[ys][lane] = acc;
    __syncthreads();                        // the only barrier

    if (ys == 0) {
        float4 r = f4max(f4max(f4max(red[0][lane], red[1][lane]),
                               f4max(red[2][lane], red[3][lane])),
                         f4max(f4max(red[4][lane], red[5][lane]),
                               f4max(red[6][lane], red[7][lane])));
        ((float4*)(out + out_off))[lane] = r;
    }
}

extern "C" void kernel_launch(void* const* d_in, const int* in_sizes, int n_in,
                              void* d_out, int out_size) {
    // metadata order: topic_reps, word_reps, topic_lens(int64, unused),
    //                 para_spans, x_spans, shell_spans
    const float* topic_reps  = (const float*)d_in[0];
    const float* word_reps   = (const float*)d_in[1];
    const int*   para_spans  = (const int*)d_in[3];
    const int*   x_spans     = (const int*)d_in[4];
    const int*   shell_spans = (const int*)d_in[5];
    float* out = (float*)d_out;

    dim3 block(64, YS);                // 512 threads
    span_maxpool_row_kernel<<<ROWS_TOTAL, block>>>(
        topic_reps, word_reps, para_spans, x_spans, shell_spans, out);
}